// round 14
// baseline (speedup 1.0000x reference)
#include <cuda_runtime.h>
#include <math.h>

#define NN    48000      // total rows = WINDOW * NUM_NODES
#define EE    768000
#define NODES 2000
#define TT    24
#define HID   64
#define SCAN_B 1024
#define SCAN_NB 47       // 47*1024 = 48128 >= NN

// ---------------- packed f32x2 helpers (sm_100+) ----------------
typedef unsigned long long u64t;
__device__ __forceinline__ u64t pack2(float lo, float hi) {
    u64t r; asm("mov.b64 %0,{%1,%2};" : "=l"(r) : "f"(lo), "f"(hi)); return r;
}
__device__ __forceinline__ void unpack2(u64t v, float& lo, float& hi) {
    asm("mov.b64 {%0,%1},%2;" : "=f"(lo), "=f"(hi) : "l"(v));
}
__device__ __forceinline__ u64t fma2(u64t a, u64t b, u64t c) {
    u64t d; asm("fma.rn.f32x2 %0,%1,%2,%3;" : "=l"(d) : "l"(a), "l"(b), "l"(c)); return d;
}
// fast activations via MUFU.EX2 + MUFU.RCP (~1e-7 rel err)
__device__ __forceinline__ float sigmoid_fast(float x) {
    return __fdividef(1.0f, 1.0f + __expf(-x));
}
__device__ __forceinline__ float tanh_fast(float x) {
    return fmaf(-2.0f, __fdividef(1.0f, __expf(2.0f * x) + 1.0f), 1.0f);
}

// ---------------- device scratch (no allocations allowed) ----------------
__device__ int   d_deg[NN];
__device__ int   d_cnt[NN];
__device__ int   d_rowptr[NN + 1];
__device__ int   d_bsum[SCAN_NB];
__device__ int   d_csr[EE];
__device__ float d_dinv[NN];
__device__ __align__(16) float d_Ga[NN * HID];   // G ping
__device__ __align__(16) float d_Gb[NN * HID];   // G pong

// ---------------- degree ----------------
__global__ void k_zero_deg() {
    int i = blockIdx.x * blockDim.x + threadIdx.x;
    if (i < NN) d_deg[i] = 0;
}
__global__ void k_count(const int* __restrict__ dst) {
    int i = blockIdx.x * blockDim.x + threadIdx.x;
    if (i < EE) atomicAdd(&d_deg[dst[i]], 1);
}
__global__ void k_dinv() {
    int i = blockIdx.x * blockDim.x + threadIdx.x;
    if (i < NN) {
        d_dinv[i] = rsqrtf((float)d_deg[i] + 1.0f);
        d_cnt[i]  = 0;
    }
}

// ---------------- exclusive scan of deg -> rowptr ----------------
__global__ void k_scan1() {
    __shared__ int s[SCAN_B];
    int b = blockIdx.x, t = threadIdx.x;
    int i = b * SCAN_B + t;
    int v = (i < NN) ? d_deg[i] : 0;
    s[t] = v;
    __syncthreads();
#pragma unroll
    for (int off = 1; off < SCAN_B; off <<= 1) {
        int u = (t >= off) ? s[t - off] : 0;
        __syncthreads();
        s[t] += u;
        __syncthreads();
    }
    if (i < NN) d_rowptr[i] = s[t];             // inclusive, temp
    if (t == SCAN_B - 1) d_bsum[b] = s[t];
}
__global__ void k_scan2() {
    __shared__ int s[SCAN_NB];
    int t = threadIdx.x;
    if (t < SCAN_NB) s[t] = d_bsum[t];
    __syncthreads();
    if (t == 0) {
        int run = 0;
        for (int b = 0; b < SCAN_NB; b++) { int v = s[b]; s[b] = run; run += v; }
        d_rowptr[NN] = EE;
    }
    __syncthreads();
    if (t < SCAN_NB) d_bsum[t] = s[t];          // exclusive block offsets
}
__global__ void k_scan3() {
    int b = blockIdx.x, t = threadIdx.x;
    int i = b * SCAN_B + t;
    if (i < NN) d_rowptr[i] = d_rowptr[i] - d_deg[i] + d_bsum[b];  // exclusive
}
__global__ void k_fill(const int* __restrict__ src, const int* __restrict__ dst) {
    int e = blockIdx.x * blockDim.x + threadIdx.x;
    if (e < EE) {
        int d = dst[e];
        int p = atomicAdd(&d_cnt[d], 1);
        d_csr[d_rowptr[d] + p] = src[e];
    }
}

// ---- 4-way unrolled CSR row gather into a float4 accumulator (deep MLP) ----
__device__ __forceinline__ float4 gather_row(const float4* __restrict__ G4,
                                             int r, int lane) {
    float4 a0 = G4[r * 16 + lane];               // self term
    float4 a1 = make_float4(0.f, 0.f, 0.f, 0.f);
    float4 a2 = make_float4(0.f, 0.f, 0.f, 0.f);
    float4 a3 = make_float4(0.f, 0.f, 0.f, 0.f);
    int e = d_rowptr[r], e1 = d_rowptr[r + 1];
    for (; e + 3 < e1; e += 4) {
        int s0 = d_csr[e];
        int s1 = d_csr[e + 1];
        int s2 = d_csr[e + 2];
        int s3 = d_csr[e + 3];
        float4 v0 = G4[s0 * 16 + lane];
        float4 v1 = G4[s1 * 16 + lane];
        float4 v2 = G4[s2 * 16 + lane];
        float4 v3 = G4[s3 * 16 + lane];
        a0.x += v0.x; a0.y += v0.y; a0.z += v0.z; a0.w += v0.w;
        a1.x += v1.x; a1.y += v1.y; a1.z += v1.z; a1.w += v1.w;
        a2.x += v2.x; a2.y += v2.y; a2.z += v2.z; a2.w += v2.w;
        a3.x += v3.x; a3.y += v3.y; a3.z += v3.z; a3.w += v3.w;
    }
    for (; e < e1; ++e) {
        int s = d_csr[e];
        float4 v = G4[s * 16 + lane];
        a0.x += v.x; a0.y += v.y; a0.z += v.z; a0.w += v.w;
    }
    a0.x += a1.x; a0.y += a1.y; a0.z += a1.z; a0.w += a1.w;
    a2.x += a3.x; a2.y += a3.y; a2.z += a3.z; a2.w += a3.w;
    a0.x += a2.x; a0.y += a2.y; a0.z += a2.z; a0.w += a2.w;
    return a0;
}

// ---------------- layer-1 GEMM: g = (x @ W1) * dinv -> G ----------------
__global__ void k_gemm12(const float* __restrict__ x, const float* __restrict__ W1,
                         float* __restrict__ G) {
    __shared__ alignas(16) float sW[12 * 64];
    __shared__ alignas(16) float sH[32 * 13];
    __shared__ float sDinv[32];
    int row0 = blockIdx.x * 32;
    int tid = threadIdx.x;

    for (int i = tid; i < 12 * 64; i += 256) sW[i] = W1[i];
    if (tid < 32) sDinv[tid] = d_dinv[row0 + tid];
    for (int i = tid; i < 32 * 12; i += 256) {
        int r = i / 12, k = i - r * 12;
        sH[r * 13 + k] = x[(row0 + r) * 12 + k];
    }
    __syncthreads();

    int r  = tid >> 3;
    int c0 = (tid & 7) * 8;
    float acc[8] = {0.f, 0.f, 0.f, 0.f, 0.f, 0.f, 0.f, 0.f};
#pragma unroll
    for (int k = 0; k < 12; k++) {
        float h = sH[r * 13 + k];
#pragma unroll
        for (int j = 0; j < 8; j++) acc[j] = fmaf(h, sW[k * 64 + c0 + j], acc[j]);
    }
    float dv = sDinv[r];
    int base = (row0 + r) * 64 + c0;
#pragma unroll
    for (int j = 0; j < 8; j++) G[base + j] = acc[j] * dv;
}

// ---- fused gather + GEMM (layers 2-4):
//  h = relu(dinv * (G[r] + sum_{e} G[csr[e]]) + bPrev);  Gout = (h @ W) * dinv
#define HSTRIDE 68
__global__ void k_gather_gemm(const float* __restrict__ G, const float* __restrict__ bPrev,
                              const float* __restrict__ W, float* __restrict__ Gout) {
    __shared__ alignas(16) float sW[64 * 64];
    __shared__ alignas(16) float sH[32 * HSTRIDE];
    __shared__ float sDinv[32];
    __shared__ float sB[64];
    int row0 = blockIdx.x * 32;
    int tid = threadIdx.x;

    for (int i = tid; i < 4096; i += 256) sW[i] = W[i];
    if (tid < 64) sB[tid] = bPrev[tid];
    if (tid < 32) sDinv[tid] = d_dinv[row0 + tid];
    __syncthreads();

    // phase 1: gather 32 rows; half-warp (16 lanes, float4) per row, 2 rows each
    {
        int hw   = tid >> 4;        // 0..15
        int lane = tid & 15;
        const float4* __restrict__ G4 = (const float4*)G;
        for (int rr = hw; rr < 32; rr += 16) {
            float4 acc = gather_row(G4, row0 + rr, lane);
            float dv = sDinv[rr];
            int k0 = lane * 4;
            sH[rr * HSTRIDE + k0 + 0] = fmaxf(fmaf(dv, acc.x, sB[k0 + 0]), 0.f);
            sH[rr * HSTRIDE + k0 + 1] = fmaxf(fmaf(dv, acc.y, sB[k0 + 1]), 0.f);
            sH[rr * HSTRIDE + k0 + 2] = fmaxf(fmaf(dv, acc.z, sB[k0 + 2]), 0.f);
            sH[rr * HSTRIDE + k0 + 3] = fmaxf(fmaf(dv, acc.w, sB[k0 + 3]), 0.f);
        }
    }
    __syncthreads();

    // phase 2: GEMM (FFMA2), 8 outputs per thread
    int r  = tid >> 3;
    int c0 = (tid & 7) * 8;
    const u64t* sW2 = (const u64t*)sW;
    u64t acc2[4];
#pragma unroll
    for (int j = 0; j < 4; j++) acc2[j] = pack2(0.f, 0.f);
#pragma unroll
    for (int k = 0; k < 64; k++) {
        float h = sH[r * HSTRIDE + k];
        u64t h2 = pack2(h, h);
        int w0 = (k * 64 + c0) >> 1;
#pragma unroll
        for (int j = 0; j < 4; j++) acc2[j] = fma2(h2, sW2[w0 + j], acc2[j]);
    }
    float dv = sDinv[r];
    int base = (row0 + r) * 64 + c0;
#pragma unroll
    for (int j = 0; j < 4; j++) {
        float lo, hi;
        unpack2(acc2[j], lo, hi);
        Gout[base + 2 * j]     = lo * dv;
        Gout[base + 2 * j + 1] = hi * dv;
    }
}

// ------- fused final-gather + 2-layer LSTM + head: 4 nodes per CTA -------
__global__ void __launch_bounds__(256, 1)
k_lstm(const float* __restrict__ Gfin, const float* __restrict__ b4,
       const float* __restrict__ Wih0, const float* __restrict__ Whh0,
       const float* __restrict__ bih0, const float* __restrict__ bhh0,
       const float* __restrict__ Wih1, const float* __restrict__ Whh1,
       const float* __restrict__ bih1, const float* __restrict__ bhh1,
       const float* __restrict__ Wout, const float* __restrict__ bout,
       float* __restrict__ out) {
    int n0 = blockIdx.x * 4;     // first of four nodes
    int g = threadIdx.x;         // gate row 0..255 (i,f,g,o blocks of 64)
    int gtype = g >> 6;

    __shared__ alignas(16) float xs[4][TT][64];  // layer-0 inputs (gathered)
    __shared__ alignas(16) float ys[4][TT][64];  // layer-0 outputs
    __shared__ alignas(16) float sh[4][64];
    __shared__ alignas(16) float sgate[4][256];
    __shared__ float sB4[64];

    if (g < 64) sB4[g] = b4[g];
    __syncthreads();

    // fused final gather: 96 rows (24 steps x 4 nodes), half-warp/row float4
    {
        int hw   = g >> 4;          // 0..15
        int lane = g & 15;
        const float4* __restrict__ G4 = (const float4*)Gfin;
        for (int rr = hw; rr < 96; rr += 16) {
            int t = rr >> 2, v = rr & 3;
            int row = t * NODES + n0 + v;
            float4 acc = gather_row(G4, row, lane);
            float dv = d_dinv[row];
            int k0 = lane * 4;
            xs[v][t][k0 + 0] = fmaxf(fmaf(dv, acc.x, sB4[k0 + 0]), 0.f);
            xs[v][t][k0 + 1] = fmaxf(fmaf(dv, acc.y, sB4[k0 + 1]), 0.f);
            xs[v][t][k0 + 2] = fmaxf(fmaf(dv, acc.z, sB4[k0 + 2]), 0.f);
            xs[v][t][k0 + 3] = fmaxf(fmaf(dv, acc.w, sB4[k0 + 3]), 0.f);
        }
    }

    // packed weight rows: 32 x f32x2 per matrix (rows are 256B-aligned)
    u64t wih2[32], whh2[32];
    {
        const u64t* wi = (const u64t*)(Wih0 + g * 64);
        const u64t* wh = (const u64t*)(Whh0 + g * 64);
#pragma unroll
        for (int k = 0; k < 32; k++) { wih2[k] = wi[k]; whh2[k] = wh[k]; }
    }
    float bsum = bih0[g] + bhh0[g];
    float creg = 0.f;            // cell state: thread g owns node g>>6, cell g&63
    sh[g >> 6][g & 63] = 0.f;
    __syncthreads();

    const u64t* shA = (const u64t*)&sh[0][0];
    const u64t* shB = (const u64t*)&sh[1][0];
    const u64t* shC = (const u64t*)&sh[2][0];
    const u64t* shD = (const u64t*)&sh[3][0];

    // ---- layer 0 ----
    for (int t = 0; t < TT; t++) {
        const u64t* xA = (const u64t*)&xs[0][t][0];
        const u64t* xB = (const u64t*)&xs[1][t][0];
        const u64t* xC = (const u64t*)&xs[2][t][0];
        const u64t* xD = (const u64t*)&xs[3][t][0];
        u64t aA = pack2(bsum, 0.f), aB = pack2(bsum, 0.f);
        u64t aC = pack2(bsum, 0.f), aD = pack2(bsum, 0.f);
#pragma unroll
        for (int k = 0; k < 32; k++) {
            aA = fma2(wih2[k], xA[k], aA);
            aB = fma2(wih2[k], xB[k], aB);
            aC = fma2(wih2[k], xC[k], aC);
            aD = fma2(wih2[k], xD[k], aD);
        }
#pragma unroll
        for (int k = 0; k < 32; k++) {
            aA = fma2(whh2[k], shA[k], aA);
            aB = fma2(whh2[k], shB[k], aB);
            aC = fma2(whh2[k], shC[k], aC);
            aD = fma2(whh2[k], shD[k], aD);
        }
        float lo, hi, vA, vB, vC, vD;
        unpack2(aA, lo, hi); vA = lo + hi;
        unpack2(aB, lo, hi); vB = lo + hi;
        unpack2(aC, lo, hi); vC = lo + hi;
        unpack2(aD, lo, hi); vD = lo + hi;
        if (gtype == 2) {
            vA = tanh_fast(vA); vB = tanh_fast(vB);
            vC = tanh_fast(vC); vD = tanh_fast(vD);
        } else {
            vA = sigmoid_fast(vA); vB = sigmoid_fast(vB);
            vC = sigmoid_fast(vC); vD = sigmoid_fast(vD);
        }
        sgate[0][g] = vA; sgate[1][g] = vB; sgate[2][g] = vC; sgate[3][g] = vD;
        __syncthreads();
        {
            int v = g >> 6, j = g & 63;
            float i_ = sgate[v][j], f_ = sgate[v][64 + j];
            float g_ = sgate[v][128 + j], o_ = sgate[v][192 + j];
            creg = f_ * creg + i_ * g_;
            float h = o_ * tanh_fast(creg);
            sh[v][j] = h;
            ys[v][t][j] = h;
        }
        __syncthreads();
    }

    // ---- layer 1 ----
    {
        const u64t* wi = (const u64t*)(Wih1 + g * 64);
        const u64t* wh = (const u64t*)(Whh1 + g * 64);
#pragma unroll
        for (int k = 0; k < 32; k++) { wih2[k] = wi[k]; whh2[k] = wh[k]; }
    }
    bsum = bih1[g] + bhh1[g];
    creg = 0.f;
    sh[g >> 6][g & 63] = 0.f;
    __syncthreads();

    for (int t = 0; t < TT; t++) {
        const u64t* yA = (const u64t*)&ys[0][t][0];
        const u64t* yB = (const u64t*)&ys[1][t][0];
        const u64t* yC = (const u64t*)&ys[2][t][0];
        const u64t* yD = (const u64t*)&ys[3][t][0];
        u64t aA = pack2(bsum, 0.f), aB = pack2(bsum, 0.f);
        u64t aC = pack2(bsum, 0.f), aD = pack2(bsum, 0.f);
#pragma unroll
        for (int k = 0; k < 32; k++) {
            aA = fma2(wih2[k], yA[k], aA);
            aB = fma2(wih2[k], yB[k], aB);
            aC = fma2(wih2[k], yC[k], aC);
            aD = fma2(wih2[k], yD[k], aD);
        }
#pragma unroll
        for (int k = 0; k < 32; k++) {
            aA = fma2(whh2[k], shA[k], aA);
            aB = fma2(whh2[k], shB[k], aB);
            aC = fma2(whh2[k], shC[k], aC);
            aD = fma2(whh2[k], shD[k], aD);
        }
        float lo, hi, vA, vB, vC, vD;
        unpack2(aA, lo, hi); vA = lo + hi;
        unpack2(aB, lo, hi); vB = lo + hi;
        unpack2(aC, lo, hi); vC = lo + hi;
        unpack2(aD, lo, hi); vD = lo + hi;
        if (gtype == 2) {
            vA = tanh_fast(vA); vB = tanh_fast(vB);
            vC = tanh_fast(vC); vD = tanh_fast(vD);
        } else {
            vA = sigmoid_fast(vA); vB = sigmoid_fast(vB);
            vC = sigmoid_fast(vC); vD = sigmoid_fast(vD);
        }
        sgate[0][g] = vA; sgate[1][g] = vB; sgate[2][g] = vC; sgate[3][g] = vD;
        __syncthreads();
        {
            int v = g >> 6, j = g & 63;
            float i_ = sgate[v][j], f_ = sgate[v][64 + j];
            float g_ = sgate[v][128 + j], o_ = sgate[v][192 + j];
            creg = f_ * creg + i_ * g_;
            float h = o_ * tanh_fast(creg);
            sh[v][j] = h;
        }
        __syncthreads();
    }

    // ---- output projection: 4 nodes x 96 outputs = 384 ----
    for (int i = g; i < 384; i += 256) {
        int v = i / 96;
        int o = i - v * 96;
        float a = bout[o];
#pragma unroll
        for (int k = 0; k < 64; k++) a = fmaf(sh[v][k], Wout[k * 96 + o], a);
        out[(n0 + v) * 96 + o] = a;
    }
}

// ---------------- launch ----------------
extern "C" void kernel_launch(void* const* d_in, const int* in_sizes, int n_in,
                              void* d_out, int out_size) {
    const float* x    = (const float*)d_in[0];
    const int*   ei   = (const int*)  d_in[1];
    const float* W1   = (const float*)d_in[2];
    const float* b1   = (const float*)d_in[3];
    const float* W2   = (const float*)d_in[4];
    const float* b2   = (const float*)d_in[5];
    const float* W3   = (const float*)d_in[6];
    const float* b3   = (const float*)d_in[7];
    const float* W4   = (const float*)d_in[8];
    const float* b4   = (const float*)d_in[9];
    const float* Wih0 = (const float*)d_in[10];
    const float* Whh0 = (const float*)d_in[11];
    const float* bih0 = (const float*)d_in[12];
    const float* bhh0 = (const float*)d_in[13];
    const float* Wih1 = (const float*)d_in[14];
    const float* Whh1 = (const float*)d_in[15];
    const float* bih1 = (const float*)d_in[16];
    const float* bhh1 = (const float*)d_in[17];
    const float* Wout = (const float*)d_in[18];
    const float* bout = (const float*)d_in[19];
    float* out = (float*)d_out;

    const int* src = ei;
    const int* dst = ei + EE;

    float *Ga, *Gb;
    cudaGetSymbolAddress((void**)&Ga, d_Ga);
    cudaGetSymbolAddress((void**)&Gb, d_Gb);

    // graph preprocessing: degree, dinv, CSR
    k_zero_deg<<<(NN + 255) / 256, 256>>>();
    k_count<<<(EE + 255) / 256, 256>>>(dst);
    k_dinv<<<(NN + 255) / 256, 256>>>();
    k_scan1<<<SCAN_NB, SCAN_B>>>();
    k_scan2<<<1, 64>>>();
    k_scan3<<<SCAN_NB, SCAN_B>>>();
    k_fill<<<(EE + 255) / 256, 256>>>(src, dst);

    // layer 1 GEMM
    k_gemm12<<<NN / 32, 256>>>(x, W1, Ga);
    // layers 2-4: fused gather+GEMM
    k_gather_gemm<<<NN / 32, 256>>>(Ga, b1, W2, Gb);
    k_gather_gemm<<<NN / 32, 256>>>(Gb, b2, W3, Ga);
    k_gather_gemm<<<NN / 32, 256>>>(Ga, b3, W4, Gb);
    // fused final-gather + LSTM x2 + head (4 nodes per CTA)
    k_lstm<<<NODES / 4, 256>>>(Gb, b4, Wih0, Whh0, bih0, bhh0,
                               Wih1, Whh1, bih1, bhh1, Wout, bout, out);
}

// round 16
// speedup vs baseline: 1.0032x; 1.0032x over previous
#include <cuda_runtime.h>
#include <math.h>

#define NN    48000      // total rows = WINDOW * NUM_NODES
#define EE    768000
#define NODES 2000
#define TT    24
#define HID   64
#define SCAN_B 1024
#define SCAN_NB 47       // 47*1024 = 48128 >= NN

// ---------------- packed f32x2 helpers (sm_100+) ----------------
typedef unsigned long long u64t;
__device__ __forceinline__ u64t pack2(float lo, float hi) {
    u64t r; asm("mov.b64 %0,{%1,%2};" : "=l"(r) : "f"(lo), "f"(hi)); return r;
}
__device__ __forceinline__ void unpack2(u64t v, float& lo, float& hi) {
    asm("mov.b64 {%0,%1},%2;" : "=f"(lo), "=f"(hi) : "l"(v));
}
__device__ __forceinline__ u64t fma2(u64t a, u64t b, u64t c) {
    u64t d; asm("fma.rn.f32x2 %0,%1,%2,%3;" : "=l"(d) : "l"(a), "l"(b), "l"(c)); return d;
}
// fast activations via MUFU.EX2 + MUFU.RCP (~1e-7 rel err)
__device__ __forceinline__ float sigmoid_fast(float x) {
    return __fdividef(1.0f, 1.0f + __expf(-x));
}
__device__ __forceinline__ float tanh_fast(float x) {
    return fmaf(-2.0f, __fdividef(1.0f, __expf(2.0f * x) + 1.0f), 1.0f);
}

// ---------------- device scratch (no allocations allowed) ----------------
// d_deg / d_cnt invariant: zero at entry of every kernel_launch call.
// Zero-initialized at module load; re-zeroed by k_scan1 each call.
__device__ int   d_deg[NN];
__device__ int   d_cnt[NN];
__device__ int   d_rowptr[NN + 1];
__device__ int   d_bsum[SCAN_NB];
__device__ int   d_csr[EE];
__device__ float d_dinv[NN];
__device__ __align__(16) float d_Ga[NN * HID];   // G ping
__device__ __align__(16) float d_Gb[NN * HID];   // G pong

// ---------------- degree count ----------------
__global__ void k_count(const int* __restrict__ dst) {
    int i = blockIdx.x * blockDim.x + threadIdx.x;
    if (i < EE) atomicAdd(&d_deg[dst[i]], 1);
}

// ---- fused: block-exclusive scan of deg -> rowptr, dinv, deg/cnt re-zero ----
__global__ void k_scan1() {
    __shared__ int s[SCAN_B];
    int b = blockIdx.x, t = threadIdx.x;
    int i = b * SCAN_B + t;
    int v = (i < NN) ? d_deg[i] : 0;
    s[t] = v;
    __syncthreads();
#pragma unroll
    for (int off = 1; off < SCAN_B; off <<= 1) {
        int u = (t >= off) ? s[t - off] : 0;
        __syncthreads();
        s[t] += u;
        __syncthreads();
    }
    if (i < NN) {
        d_rowptr[i] = s[t] - v;                  // block-exclusive scan
        d_dinv[i]   = rsqrtf((float)v + 1.0f);
        d_deg[i]    = 0;                         // restore invariant for next call
        d_cnt[i]    = 0;
    }
    if (t == SCAN_B - 1) d_bsum[b] = s[t];       // block total
}

// ---- apply block offsets (each block sums <=47 block totals serially) ----
__global__ void k_scan3() {
    __shared__ int soff;
    int b = blockIdx.x, t = threadIdx.x;
    if (t == 0) {
        int run = 0;
        for (int bb = 0; bb < b; bb++) run += d_bsum[bb];
        soff = run;
        if (b == 0) d_rowptr[NN] = EE;
    }
    __syncthreads();
    int i = b * SCAN_B + t;
    if (i < NN) d_rowptr[i] += soff;
}

__global__ void k_fill(const int* __restrict__ src, const int* __restrict__ dst) {
    int e = blockIdx.x * blockDim.x + threadIdx.x;
    if (e < EE) {
        int d = dst[e];
        int p = atomicAdd(&d_cnt[d], 1);
        d_csr[d_rowptr[d] + p] = src[e];
    }
}

// ---- 4-way unrolled CSR row gather into a float4 accumulator (deep MLP) ----
__device__ __forceinline__ float4 gather_row(const float4* __restrict__ G4,
                                             int r, int lane) {
    float4 a0 = G4[r * 16 + lane];               // self term
    float4 a1 = make_float4(0.f, 0.f, 0.f, 0.f);
    float4 a2 = make_float4(0.f, 0.f, 0.f, 0.f);
    float4 a3 = make_float4(0.f, 0.f, 0.f, 0.f);
    int e = d_rowptr[r], e1 = d_rowptr[r + 1];
    for (; e + 3 < e1; e += 4) {
        int s0 = d_csr[e];
        int s1 = d_csr[e + 1];
        int s2 = d_csr[e + 2];
        int s3 = d_csr[e + 3];
        float4 v0 = G4[s0 * 16 + lane];
        float4 v1 = G4[s1 * 16 + lane];
        float4 v2 = G4[s2 * 16 + lane];
        float4 v3 = G4[s3 * 16 + lane];
        a0.x += v0.x; a0.y += v0.y; a0.z += v0.z; a0.w += v0.w;
        a1.x += v1.x; a1.y += v1.y; a1.z += v1.z; a1.w += v1.w;
        a2.x += v2.x; a2.y += v2.y; a2.z += v2.z; a2.w += v2.w;
        a3.x += v3.x; a3.y += v3.y; a3.z += v3.z; a3.w += v3.w;
    }
    for (; e < e1; ++e) {
        int s = d_csr[e];
        float4 v = G4[s * 16 + lane];
        a0.x += v.x; a0.y += v.y; a0.z += v.z; a0.w += v.w;
    }
    a0.x += a1.x; a0.y += a1.y; a0.z += a1.z; a0.w += a1.w;
    a2.x += a3.x; a2.y += a3.y; a2.z += a3.z; a2.w += a3.w;
    a0.x += a2.x; a0.y += a2.y; a0.z += a2.z; a0.w += a2.w;
    return a0;
}

// ---------------- layer-1 GEMM: g = (x @ W1) * dinv -> G ----------------
__global__ void k_gemm12(const float* __restrict__ x, const float* __restrict__ W1,
                         float* __restrict__ G) {
    __shared__ alignas(16) float sW[12 * 64];
    __shared__ alignas(16) float sH[32 * 13];
    __shared__ float sDinv[32];
    int row0 = blockIdx.x * 32;
    int tid = threadIdx.x;

    for (int i = tid; i < 12 * 64; i += 256) sW[i] = W1[i];
    if (tid < 32) sDinv[tid] = d_dinv[row0 + tid];
    for (int i = tid; i < 32 * 12; i += 256) {
        int r = i / 12, k = i - r * 12;
        sH[r * 13 + k] = x[(row0 + r) * 12 + k];
    }
    __syncthreads();

    int r  = tid >> 3;
    int c0 = (tid & 7) * 8;
    float acc[8] = {0.f, 0.f, 0.f, 0.f, 0.f, 0.f, 0.f, 0.f};
#pragma unroll
    for (int k = 0; k < 12; k++) {
        float h = sH[r * 13 + k];
#pragma unroll
        for (int j = 0; j < 8; j++) acc[j] = fmaf(h, sW[k * 64 + c0 + j], acc[j]);
    }
    float dv = sDinv[r];
    int base = (row0 + r) * 64 + c0;
#pragma unroll
    for (int j = 0; j < 8; j++) G[base + j] = acc[j] * dv;
}

// ---- fused gather + GEMM (layers 2-4):
//  h = relu(dinv * (G[r] + sum_{e} G[csr[e]]) + bPrev);  Gout = (h @ W) * dinv
#define HSTRIDE 68
__global__ void k_gather_gemm(const float* __restrict__ G, const float* __restrict__ bPrev,
                              const float* __restrict__ W, float* __restrict__ Gout) {
    __shared__ alignas(16) float sW[64 * 64];
    __shared__ alignas(16) float sH[32 * HSTRIDE];
    __shared__ float sDinv[32];
    __shared__ float sB[64];
    int row0 = blockIdx.x * 32;
    int tid = threadIdx.x;

    for (int i = tid; i < 4096; i += 256) sW[i] = W[i];
    if (tid < 64) sB[tid] = bPrev[tid];
    if (tid < 32) sDinv[tid] = d_dinv[row0 + tid];
    __syncthreads();

    // phase 1: gather 32 rows; half-warp (16 lanes, float4) per row, 2 rows each
    {
        int hw   = tid >> 4;        // 0..15
        int lane = tid & 15;
        const float4* __restrict__ G4 = (const float4*)G;
        for (int rr = hw; rr < 32; rr += 16) {
            float4 acc = gather_row(G4, row0 + rr, lane);
            float dv = sDinv[rr];
            int k0 = lane * 4;
            sH[rr * HSTRIDE + k0 + 0] = fmaxf(fmaf(dv, acc.x, sB[k0 + 0]), 0.f);
            sH[rr * HSTRIDE + k0 + 1] = fmaxf(fmaf(dv, acc.y, sB[k0 + 1]), 0.f);
            sH[rr * HSTRIDE + k0 + 2] = fmaxf(fmaf(dv, acc.z, sB[k0 + 2]), 0.f);
            sH[rr * HSTRIDE + k0 + 3] = fmaxf(fmaf(dv, acc.w, sB[k0 + 3]), 0.f);
        }
    }
    __syncthreads();

    // phase 2: GEMM (FFMA2), 8 outputs per thread
    int r  = tid >> 3;
    int c0 = (tid & 7) * 8;
    const u64t* sW2 = (const u64t*)sW;
    u64t acc2[4];
#pragma unroll
    for (int j = 0; j < 4; j++) acc2[j] = pack2(0.f, 0.f);
#pragma unroll
    for (int k = 0; k < 64; k++) {
        float h = sH[r * HSTRIDE + k];
        u64t h2 = pack2(h, h);
        int w0 = (k * 64 + c0) >> 1;
#pragma unroll
        for (int j = 0; j < 4; j++) acc2[j] = fma2(h2, sW2[w0 + j], acc2[j]);
    }
    float dv = sDinv[r];
    int base = (row0 + r) * 64 + c0;
#pragma unroll
    for (int j = 0; j < 4; j++) {
        float lo, hi;
        unpack2(acc2[j], lo, hi);
        Gout[base + 2 * j]     = lo * dv;
        Gout[base + 2 * j + 1] = hi * dv;
    }
}

// ------- fused final-gather + 2-layer LSTM + head: 4 nodes per CTA -------
__global__ void __launch_bounds__(256, 1)
k_lstm(const float* __restrict__ Gfin, const float* __restrict__ b4,
       const float* __restrict__ Wih0, const float* __restrict__ Whh0,
       const float* __restrict__ bih0, const float* __restrict__ bhh0,
       const float* __restrict__ Wih1, const float* __restrict__ Whh1,
       const float* __restrict__ bih1, const float* __restrict__ bhh1,
       const float* __restrict__ Wout, const float* __restrict__ bout,
       float* __restrict__ out) {
    int n0 = blockIdx.x * 4;     // first of four nodes
    int g = threadIdx.x;         // gate row 0..255 (i,f,g,o blocks of 64)
    int gtype = g >> 6;

    __shared__ alignas(16) float xs[4][TT][64];  // layer-0 inputs (gathered)
    __shared__ alignas(16) float ys[4][TT][64];  // layer-0 outputs
    __shared__ alignas(16) float sh[4][64];
    __shared__ alignas(16) float sgate[4][256];
    __shared__ float sB4[64];

    if (g < 64) sB4[g] = b4[g];
    __syncthreads();

    // fused final gather: 96 rows (24 steps x 4 nodes), half-warp/row float4
    {
        int hw   = g >> 4;          // 0..15
        int lane = g & 15;
        const float4* __restrict__ G4 = (const float4*)Gfin;
        for (int rr = hw; rr < 96; rr += 16) {
            int t = rr >> 2, v = rr & 3;
            int row = t * NODES + n0 + v;
            float4 acc = gather_row(G4, row, lane);
            float dv = d_dinv[row];
            int k0 = lane * 4;
            xs[v][t][k0 + 0] = fmaxf(fmaf(dv, acc.x, sB4[k0 + 0]), 0.f);
            xs[v][t][k0 + 1] = fmaxf(fmaf(dv, acc.y, sB4[k0 + 1]), 0.f);
            xs[v][t][k0 + 2] = fmaxf(fmaf(dv, acc.z, sB4[k0 + 2]), 0.f);
            xs[v][t][k0 + 3] = fmaxf(fmaf(dv, acc.w, sB4[k0 + 3]), 0.f);
        }
    }

    // packed weight rows: 32 x f32x2 per matrix (rows are 256B-aligned)
    u64t wih2[32], whh2[32];
    {
        const u64t* wi = (const u64t*)(Wih0 + g * 64);
        const u64t* wh = (const u64t*)(Whh0 + g * 64);
#pragma unroll
        for (int k = 0; k < 32; k++) { wih2[k] = wi[k]; whh2[k] = wh[k]; }
    }
    float bsum = bih0[g] + bhh0[g];
    float creg = 0.f;            // cell state: thread g owns node g>>6, cell g&63
    sh[g >> 6][g & 63] = 0.f;
    __syncthreads();

    const u64t* shA = (const u64t*)&sh[0][0];
    const u64t* shB = (const u64t*)&sh[1][0];
    const u64t* shC = (const u64t*)&sh[2][0];
    const u64t* shD = (const u64t*)&sh[3][0];

    // ---- layer 0 ----
    for (int t = 0; t < TT; t++) {
        const u64t* xA = (const u64t*)&xs[0][t][0];
        const u64t* xB = (const u64t*)&xs[1][t][0];
        const u64t* xC = (const u64t*)&xs[2][t][0];
        const u64t* xD = (const u64t*)&xs[3][t][0];
        u64t aA = pack2(bsum, 0.f), aB = pack2(bsum, 0.f);
        u64t aC = pack2(bsum, 0.f), aD = pack2(bsum, 0.f);
#pragma unroll
        for (int k = 0; k < 32; k++) {
            aA = fma2(wih2[k], xA[k], aA);
            aB = fma2(wih2[k], xB[k], aB);
            aC = fma2(wih2[k], xC[k], aC);
            aD = fma2(wih2[k], xD[k], aD);
        }
#pragma unroll
        for (int k = 0; k < 32; k++) {
            aA = fma2(whh2[k], shA[k], aA);
            aB = fma2(whh2[k], shB[k], aB);
            aC = fma2(whh2[k], shC[k], aC);
            aD = fma2(whh2[k], shD[k], aD);
        }
        float lo, hi, vA, vB, vC, vD;
        unpack2(aA, lo, hi); vA = lo + hi;
        unpack2(aB, lo, hi); vB = lo + hi;
        unpack2(aC, lo, hi); vC = lo + hi;
        unpack2(aD, lo, hi); vD = lo + hi;
        if (gtype == 2) {
            vA = tanh_fast(vA); vB = tanh_fast(vB);
            vC = tanh_fast(vC); vD = tanh_fast(vD);
        } else {
            vA = sigmoid_fast(vA); vB = sigmoid_fast(vB);
            vC = sigmoid_fast(vC); vD = sigmoid_fast(vD);
        }
        sgate[0][g] = vA; sgate[1][g] = vB; sgate[2][g] = vC; sgate[3][g] = vD;
        __syncthreads();
        {
            int v = g >> 6, j = g & 63;
            float i_ = sgate[v][j], f_ = sgate[v][64 + j];
            float g_ = sgate[v][128 + j], o_ = sgate[v][192 + j];
            creg = f_ * creg + i_ * g_;
            float h = o_ * tanh_fast(creg);
            sh[v][j] = h;
            ys[v][t][j] = h;
        }
        __syncthreads();
    }

    // ---- layer 1 ----
    {
        const u64t* wi = (const u64t*)(Wih1 + g * 64);
        const u64t* wh = (const u64t*)(Whh1 + g * 64);
#pragma unroll
        for (int k = 0; k < 32; k++) { wih2[k] = wi[k]; whh2[k] = wh[k]; }
    }
    bsum = bih1[g] + bhh1[g];
    creg = 0.f;
    sh[g >> 6][g & 63] = 0.f;
    __syncthreads();

    for (int t = 0; t < TT; t++) {
        const u64t* yA = (const u64t*)&ys[0][t][0];
        const u64t* yB = (const u64t*)&ys[1][t][0];
        const u64t* yC = (const u64t*)&ys[2][t][0];
        const u64t* yD = (const u64t*)&ys[3][t][0];
        u64t aA = pack2(bsum, 0.f), aB = pack2(bsum, 0.f);
        u64t aC = pack2(bsum, 0.f), aD = pack2(bsum, 0.f);
#pragma unroll
        for (int k = 0; k < 32; k++) {
            aA = fma2(wih2[k], yA[k], aA);
            aB = fma2(wih2[k], yB[k], aB);
            aC = fma2(wih2[k], yC[k], aC);
            aD = fma2(wih2[k], yD[k], aD);
        }
#pragma unroll
        for (int k = 0; k < 32; k++) {
            aA = fma2(whh2[k], shA[k], aA);
            aB = fma2(whh2[k], shB[k], aB);
            aC = fma2(whh2[k], shC[k], aC);
            aD = fma2(whh2[k], shD[k], aD);
        }
        float lo, hi, vA, vB, vC, vD;
        unpack2(aA, lo, hi); vA = lo + hi;
        unpack2(aB, lo, hi); vB = lo + hi;
        unpack2(aC, lo, hi); vC = lo + hi;
        unpack2(aD, lo, hi); vD = lo + hi;
        if (gtype == 2) {
            vA = tanh_fast(vA); vB = tanh_fast(vB);
            vC = tanh_fast(vC); vD = tanh_fast(vD);
        } else {
            vA = sigmoid_fast(vA); vB = sigmoid_fast(vB);
            vC = sigmoid_fast(vC); vD = sigmoid_fast(vD);
        }
        sgate[0][g] = vA; sgate[1][g] = vB; sgate[2][g] = vC; sgate[3][g] = vD;
        __syncthreads();
        {
            int v = g >> 6, j = g & 63;
            float i_ = sgate[v][j], f_ = sgate[v][64 + j];
            float g_ = sgate[v][128 + j], o_ = sgate[v][192 + j];
            creg = f_ * creg + i_ * g_;
            float h = o_ * tanh_fast(creg);
            sh[v][j] = h;
        }
        __syncthreads();
    }

    // ---- output projection: 4 nodes x 96 outputs = 384 ----
    for (int i = g; i < 384; i += 256) {
        int v = i / 96;
        int o = i - v * 96;
        float a = bout[o];
#pragma unroll
        for (int k = 0; k < 64; k++) a = fmaf(sh[v][k], Wout[k * 96 + o], a);
        out[(n0 + v) * 96 + o] = a;
    }
}

// ---------------- launch ----------------
extern "C" void kernel_launch(void* const* d_in, const int* in_sizes, int n_in,
                              void* d_out, int out_size) {
    const float* x    = (const float*)d_in[0];
    const int*   ei   = (const int*)  d_in[1];
    const float* W1   = (const float*)d_in[2];
    const float* b1   = (const float*)d_in[3];
    const float* W2   = (const float*)d_in[4];
    const float* b2   = (const float*)d_in[5];
    const float* W3   = (const float*)d_in[6];
    const float* b3   = (const float*)d_in[7];
    const float* W4   = (const float*)d_in[8];
    const float* b4   = (const float*)d_in[9];
    const float* Wih0 = (const float*)d_in[10];
    const float* Whh0 = (const float*)d_in[11];
    const float* bih0 = (const float*)d_in[12];
    const float* bhh0 = (const float*)d_in[13];
    const float* Wih1 = (const float*)d_in[14];
    const float* Whh1 = (const float*)d_in[15];
    const float* bih1 = (const float*)d_in[16];
    const float* bhh1 = (const float*)d_in[17];
    const float* Wout = (const float*)d_in[18];
    const float* bout = (const float*)d_in[19];
    float* out = (float*)d_out;

    const int* src = ei;
    const int* dst = ei + EE;

    float *Ga, *Gb;
    cudaGetSymbolAddress((void**)&Ga, d_Ga);
    cudaGetSymbolAddress((void**)&Gb, d_Gb);

    // graph preprocessing: degree count, fused scan/dinv, offsets, CSR fill
    k_count<<<(EE + 255) / 256, 256>>>(dst);
    k_scan1<<<SCAN_NB, SCAN_B>>>();
    k_scan3<<<SCAN_NB, SCAN_B>>>();
    k_fill<<<(EE + 255) / 256, 256>>>(src, dst);

    // layer 1 GEMM
    k_gemm12<<<NN / 32, 256>>>(x, W1, Ga);
    // layers 2-4: fused gather+GEMM
    k_gather_gemm<<<NN / 32, 256>>>(Ga, b1, W2, Gb);
    k_gather_gemm<<<NN / 32, 256>>>(Gb, b2, W3, Ga);
    k_gather_gemm<<<NN / 32, 256>>>(Ga, b3, W4, Gb);
    // fused final-gather + LSTM x2 + head (4 nodes per CTA)
    k_lstm<<<NODES / 4, 256>>>(Gb, b4, Wih0, Whh0, bih0, bhh0,
                               Wih1, Whh1, bih1, bhh1, Wout, bout, out);
}